// round 2
// baseline (speedup 1.0000x reference)
#include <cuda_runtime.h>
#include <cuda_bf16.h>
#include <cstddef>

// ---------------------------------------------------------------------------
// Problem: out = relu(x @ W + b1) @ W2 + b2
// where W[a,b] = sum_i sum_j (Z1^j g_i)[a] * (Zm1T^j h_i)[b]
//             = sum_i sum_j ge_i[a - j + 512] * hs_i[b + j]
//   ge_i[k] = g_i[k mod 512]                     (cyclic extension, k in [0,1024))
//   hs_i[k] = h_i[k]        for k < 512
//           = -h_i[k - 512] for k >= 512         (sign-folded negacyclic ext.)
//
// Shapes: x (65536,512) f32, G/H (512,4), b1 (512), W2 (512,512), b2 (512)
// ---------------------------------------------------------------------------

#define NDIM 512
#define RDIM 4
#define BATCH 65536

// Scratch (allocation-free rule: use __device__ globals)
__device__ float g_W[NDIM * NDIM];            // 1 MB
__device__ float g_h[(size_t)BATCH * NDIM];   // 128 MB

// ---------------------------------------------------------------------------
// Kernel 1: build W (512x512) from G,H.
// Grid (8,8), 256 threads. Each block computes a 64x64 tile of W; each thread
// a 4x4 register tile with sliding windows over the extended g/h arrays.
// ---------------------------------------------------------------------------
__global__ __launch_bounds__(256)
void krylov_w_kernel(const float* __restrict__ G, const float* __restrict__ H,
                     float* __restrict__ W) {
    __shared__ float ge[RDIM][1024];
    __shared__ float hs[RDIM][1024];

    const int tid = threadIdx.x;
    for (int idx = tid; idx < RDIM * 1024; idx += 256) {
        int i = idx >> 10;
        int k = idx & 1023;
        ge[i][k] = G[(k & (NDIM - 1)) * RDIM + i];
        hs[i][k] = (k < NDIM) ? H[k * RDIM + i] : -H[(k - NDIM) * RDIM + i];
    }
    __syncthreads();

    const int a0 = blockIdx.y * 64 + (tid >> 4) * 4;   // W row base for this thread
    const int b0 = blockIdx.x * 64 + (tid & 15) * 4;   // W col base for this thread

    float acc[4][4] = {};

    for (int i = 0; i < RDIM; ++i) {
        float ga[4], hb[4];
#pragma unroll
        for (int d = 0; d < 4; ++d) ga[d] = ge[i][512 + a0 + d];
#pragma unroll
        for (int e = 0; e < 4; ++e) hb[e] = hs[i][b0 + e];

#pragma unroll 4
        for (int j = 0; j < NDIM; ++j) {
#pragma unroll
            for (int d = 0; d < 4; ++d)
#pragma unroll
                for (int e = 0; e < 4; ++e)
                    acc[d][e] = fmaf(ga[d], hb[e], acc[d][e]);
            // slide windows for j+1 (loads stay in-bounds even at j=511)
            ga[3] = ga[2]; ga[2] = ga[1]; ga[1] = ga[0];
            ga[0] = ge[i][512 + a0 - (j + 1)];
            hb[0] = hb[1]; hb[1] = hb[2]; hb[2] = hb[3];
            hb[3] = hs[i][b0 + 3 + (j + 1)];
        }
    }

#pragma unroll
    for (int d = 0; d < 4; ++d)
#pragma unroll
        for (int e = 0; e < 4; ++e)
            W[(a0 + d) * NDIM + (b0 + e)] = acc[d][e];
}

// ---------------------------------------------------------------------------
// Kernel 2: C[M,512] = act(A[M,512] @ B[512,512] + bias)
// Block tile 128x128, K-chunk 32, 256 threads, 8x8 register tile per thread.
// relu flag selects activation.
// ---------------------------------------------------------------------------
__global__ __launch_bounds__(256)
void gemm_bias_act(const float* __restrict__ A, const float* __restrict__ B,
                   const float* __restrict__ bias, float* __restrict__ C,
                   int relu) {
    __shared__ float As[32][132];   // As[k][m] (transposed A chunk, padded)
    __shared__ float Bs[32][128];   // Bs[k][n]

    const int tid = threadIdx.x;
    const int m0 = blockIdx.y * 128;
    const int n0 = blockIdx.x * 128;
    const int tm = (tid >> 4) * 8;
    const int tn = (tid & 15) * 8;

    float acc[8][8] = {};

    for (int k0 = 0; k0 < NDIM; k0 += 32) {
        // Load A chunk (128 rows x 32 k) -> As[k][m]
#pragma unroll
        for (int q = 0; q < 4; ++q) {
            int f   = tid + q * 256;       // 0..1023 float4 slots
            int row = f >> 3;              // 8 float4 per row
            int c4  = (f & 7) << 2;
            float4 v = *(const float4*)&A[(size_t)(m0 + row) * NDIM + k0 + c4];
            As[c4 + 0][row] = v.x;
            As[c4 + 1][row] = v.y;
            As[c4 + 2][row] = v.z;
            As[c4 + 3][row] = v.w;
        }
        // Load B chunk (32 k x 128 n) -> Bs[k][n]
#pragma unroll
        for (int q = 0; q < 4; ++q) {
            int f   = tid + q * 256;
            int row = f >> 5;              // 32 float4 per row
            int c4  = (f & 31) << 2;
            *(float4*)&Bs[row][c4] =
                *(const float4*)&B[(size_t)(k0 + row) * NDIM + n0 + c4];
        }
        __syncthreads();

#pragma unroll 8
        for (int k = 0; k < 32; ++k) {
            float a[8], b[8];
            *(float4*)&a[0] = *(const float4*)&As[k][tm];
            *(float4*)&a[4] = *(const float4*)&As[k][tm + 4];
            *(float4*)&b[0] = *(const float4*)&Bs[k][tn];
            *(float4*)&b[4] = *(const float4*)&Bs[k][tn + 4];
#pragma unroll
            for (int d = 0; d < 8; ++d)
#pragma unroll
                for (int e = 0; e < 8; ++e)
                    acc[d][e] = fmaf(a[d], b[e], acc[d][e]);
        }
        __syncthreads();
    }

    // Epilogue: bias + optional relu, vectorized stores
    float bv[8];
#pragma unroll
    for (int e = 0; e < 8; ++e) bv[e] = __ldg(&bias[n0 + tn + e]);

#pragma unroll
    for (int d = 0; d < 8; ++d) {
#pragma unroll
        for (int e = 0; e < 8; e += 4) {
            float4 v;
            v.x = acc[d][e + 0] + bv[e + 0];
            v.y = acc[d][e + 1] + bv[e + 1];
            v.z = acc[d][e + 2] + bv[e + 2];
            v.w = acc[d][e + 3] + bv[e + 3];
            if (relu) {
                v.x = fmaxf(v.x, 0.f);
                v.y = fmaxf(v.y, 0.f);
                v.z = fmaxf(v.z, 0.f);
                v.w = fmaxf(v.w, 0.f);
            }
            *(float4*)&C[(size_t)(m0 + tm + d) * NDIM + n0 + tn + e] = v;
        }
    }
}

// ---------------------------------------------------------------------------
// Launch: W-builder, then stage-1 GEMM (relu) into scratch h, then stage-2.
// ---------------------------------------------------------------------------
extern "C" void kernel_launch(void* const* d_in, const int* in_sizes, int n_in,
                              void* d_out, int out_size) {
    const float* x  = (const float*)d_in[0];
    const float* G  = (const float*)d_in[1];
    const float* H  = (const float*)d_in[2];
    const float* b1 = (const float*)d_in[3];
    const float* W2 = (const float*)d_in[4];
    const float* b2 = (const float*)d_in[5];
    float* out = (float*)d_out;

    void *pW = nullptr, *ph = nullptr;
    cudaGetSymbolAddress(&pW, g_W);   // address query only; no alloc, capture-safe
    cudaGetSymbolAddress(&ph, g_h);
    float* Wbuf = (float*)pW;
    float* hbuf = (float*)ph;

    // 1) Build structured W (512x512)
    krylov_w_kernel<<<dim3(8, 8), 256>>>(G, H, Wbuf);

    // 2) h = relu(x @ W + b1)
    gemm_bias_act<<<dim3(NDIM / 128, BATCH / 128), 256>>>(x, Wbuf, b1, hbuf, 1);

    // 3) out = h @ W2 + b2
    gemm_bias_act<<<dim3(NDIM / 128, BATCH / 128), 256>>>(hbuf, W2, b2, out, 0);
}

// round 4
// speedup vs baseline: 2.9908x; 2.9908x over previous
#include <cuda_runtime.h>
#include <cuda_fp16.h>
#include <mma.h>
#include <cstdint>
#include <cstddef>

using namespace nvcuda;

#define NDIM  512
#define BATCH 65536

// Scratch (__device__ globals: allocation-free rule)
__device__ float  g_Wpart[16 * NDIM * NDIM];   // 16 MB per-(i,j-quarter) partials
__device__ __half g_Wtd[NDIM * 1024];          // W^T fp16, K-duplicated pairs [n][2k]
__device__ __half g_W2t[NDIM * NDIM];          // W2^T fp16 [n][k]
__device__ __half g_h[(size_t)BATCH * NDIM];   // 64 MB hidden fp16

__device__ __forceinline__ uint32_t pack_h2(__half a, __half b) {
    return (uint32_t)__half_as_ushort(a) | ((uint32_t)__half_as_ushort(b) << 16);
}

// ---------------- Kernel 1: Krylov partial W (split by i and j-quarter) ----------------
// W[a,b] = sum_i sum_j ge_i[512+a-j] * hs_i[b+j]
__global__ __launch_bounds__(256)
void krylov_part(const float* __restrict__ G, const float* __restrict__ H,
                 float* __restrict__ Wp) {
    __shared__ float ge[1024], hs[1024];
    const int tid = threadIdx.x;
    const int i  = blockIdx.z & 3;
    const int j0 = (blockIdx.z >> 2) * 128;
    for (int k = tid; k < 1024; k += 256) {
        ge[k] = G[(k & 511) * 4 + i];
        hs[k] = (k < 512) ? H[k * 4 + i] : -H[(k - 512) * 4 + i];
    }
    __syncthreads();
    const int a0 = blockIdx.y * 64 + (tid >> 4) * 4;
    const int b0 = blockIdx.x * 64 + (tid & 15) * 4;
    float acc[4][4] = {};
    float ga[4], hb[4];
#pragma unroll
    for (int d = 0; d < 4; ++d) ga[d] = ge[512 + a0 + d - j0];
#pragma unroll
    for (int e = 0; e < 4; ++e) hb[e] = hs[b0 + e + j0];
#pragma unroll 4
    for (int j = j0; j < j0 + 128; ++j) {
#pragma unroll
        for (int d = 0; d < 4; ++d)
#pragma unroll
            for (int e = 0; e < 4; ++e)
                acc[d][e] = fmaf(ga[d], hb[e], acc[d][e]);
        ga[3] = ga[2]; ga[2] = ga[1]; ga[1] = ga[0];
        ga[0] = ge[512 + a0 - (j + 1)];
        hb[0] = hb[1]; hb[1] = hb[2]; hb[2] = hb[3];
        hb[3] = hs[b0 + 3 + (j + 1)];
    }
    float* Ws = Wp + (size_t)blockIdx.z * NDIM * NDIM;
#pragma unroll
    for (int d = 0; d < 4; ++d)
#pragma unroll
        for (int e = 0; e < 4; ++e)
            Ws[(a0 + d) * NDIM + (b0 + e)] = acc[d][e];
}

// -------- Kernel 2a: Wtd[n][2k] = Wtd[n][2k+1] = fp16(sum_z Wpart[z][k][n]) --------
__global__ __launch_bounds__(256)
void pack_w(const float* __restrict__ Wp, __half* __restrict__ Wtd) {
    __shared__ float t[32][33];
    const int bx = blockIdx.x * 32, by = blockIdx.y * 32, tx = threadIdx.x;
    for (int r = threadIdx.y; r < 32; r += 8) {
        size_t o = (size_t)(bx + r) * NDIM + by + tx;
        float s = 0.f;
#pragma unroll
        for (int z = 0; z < 16; ++z) s += Wp[o + (size_t)z * NDIM * NDIM];
        t[r][tx] = s;
    }
    __syncthreads();
    for (int r = threadIdx.y; r < 32; r += 8) {
        __half v = __float2half_rn(t[tx][r]);
        ((uint32_t*)Wtd)[(size_t)(by + r) * NDIM + (bx + tx)] = pack_h2(v, v);
    }
}

// -------- Kernel 2b: W2t[n][k] = fp16(W2[k][n]) --------
__global__ __launch_bounds__(256)
void pack_w2(const float* __restrict__ W2, __half* __restrict__ W2t) {
    __shared__ float t[32][33];
    const int bx = blockIdx.x * 32, by = blockIdx.y * 32, tx = threadIdx.x;
    for (int r = threadIdx.y; r < 32; r += 8)
        t[r][tx] = W2[(size_t)(bx + r) * NDIM + by + tx];
    __syncthreads();
    for (int r = threadIdx.y; r < 32; r += 8)
        W2t[(size_t)(by + r) * NDIM + bx + tx] = __float2half_rn(t[tx][r]);
}

// ---------------- Kernel 3: wmma (HMMA) GEMM, 128x128 tile ----------------
// STAGE 1: A = x fp32 -> (hi,lo) fp16 interleaved, K'=1024; B = Wtd [n][1024].
//          C = relu(acc + b1) -> fp16 h.
// STAGE 2: A = h fp16 [m][512]; B = W2t [n][512]. C = acc + b2 -> fp32 out.
#define LDA   72              // halves per SMEM row (64 + 8 pad)
#define ABUF(b) ((b) * 36864u)
#define BBUF(b) ((b) * 36864u + 18432u)
#define SBIAS   73728u
#define SMEM_SZ 74240u        // 2 buffers (72KB) + 128 bias floats

template <int STAGE>
__global__ __launch_bounds__(256, 1)
void gemm_wmma(const void* __restrict__ Ag, const __half* __restrict__ Bg,
               const float* __restrict__ bias, void* __restrict__ Cg) {
    extern __shared__ char smem[];
    __half* smh = (__half*)smem;
    const int tid = threadIdx.x;
    const int wid = tid >> 5;
    const int wm = wid & 3;          // warp row  (4)
    const int wn = wid >> 2;         // warp col  (2)
    const int n0 = blockIdx.x * 128;
    const int m0 = blockIdx.y * 128;
    const int KK     = (STAGE == 1) ? 1024 : 512;
    const int NCHUNK = KK / 64;

    float* bias_s = (float*)(smem + SBIAS);
    if (tid < 128) bias_s[tid] = bias[n0 + tid];

    wmma::fragment<wmma::accumulator, 16, 16, 16, float> acc[2][4];
#pragma unroll
    for (int i = 0; i < 2; ++i)
#pragma unroll
        for (int j = 0; j < 4; ++j)
            wmma::fill_fragment(acc[i][j], 0.f);

    const int row = tid >> 3;        // 0..31 over 4 iters -> 128 rows
    const int seg = tid & 7;

    float4 pa[4]; uint4 pa2[4]; uint4 pb[4];

    // prefetch chunk 0
    {
        if (STAGE == 1) {
            const float* xp = (const float*)Ag + (size_t)m0 * NDIM;
#pragma unroll
            for (int q = 0; q < 4; ++q)
                pa[q] = *(const float4*)(xp + (size_t)(row + q * 32) * NDIM + seg * 4);
        } else {
            const __half* hp = (const __half*)Ag + (size_t)m0 * NDIM;
#pragma unroll
            for (int q = 0; q < 4; ++q)
                pa2[q] = *(const uint4*)(hp + (size_t)(row + q * 32) * NDIM + seg * 8);
        }
#pragma unroll
        for (int q = 0; q < 4; ++q)
            pb[q] = *(const uint4*)(Bg + (size_t)(n0 + row + q * 32) * KK + seg * 8);
    }

    for (int c = 0; c < NCHUNK; ++c) {
        const int b = c & 1;
        __half* As = smh + ABUF(b) / 2;
        __half* Bs = smh + BBUF(b) / 2;
        // ---- store prefetched chunk c to SMEM ----
        if (STAGE == 1) {
#pragma unroll
            for (int q = 0; q < 4; ++q) {
                float4 v = pa[q];
                __half h0 = __float2half_rn(v.x), h1 = __float2half_rn(v.y);
                __half h2 = __float2half_rn(v.z), h3 = __float2half_rn(v.w);
                __half l0 = __float2half_rn(v.x - __half2float(h0));
                __half l1 = __float2half_rn(v.y - __half2float(h1));
                __half l2 = __float2half_rn(v.z - __half2float(h2));
                __half l3 = __float2half_rn(v.w - __half2float(h3));
                *(uint4*)(As + (row + q * 32) * LDA + seg * 8) =
                    make_uint4(pack_h2(h0, l0), pack_h2(h1, l1),
                               pack_h2(h2, l2), pack_h2(h3, l3));
            }
        } else {
#pragma unroll
            for (int q = 0; q < 4; ++q)
                *(uint4*)(As + (row + q * 32) * LDA + seg * 8) = pa2[q];
        }
#pragma unroll
        for (int q = 0; q < 4; ++q)
            *(uint4*)(Bs + (row + q * 32) * LDA + seg * 8) = pb[q];

        // ---- prefetch chunk c+1 ----
        if (c + 1 < NCHUNK) {
            if (STAGE == 1) {
                const float* xp = (const float*)Ag + (size_t)m0 * NDIM + (c + 1) * 32;
#pragma unroll
                for (int q = 0; q < 4; ++q)
                    pa[q] = *(const float4*)(xp + (size_t)(row + q * 32) * NDIM + seg * 4);
            } else {
                const __half* hp = (const __half*)Ag + (size_t)m0 * NDIM + (c + 1) * 64;
#pragma unroll
                for (int q = 0; q < 4; ++q)
                    pa2[q] = *(const uint4*)(hp + (size_t)(row + q * 32) * NDIM + seg * 8);
            }
#pragma unroll
            for (int q = 0; q < 4; ++q)
                pb[q] = *(const uint4*)(Bg + (size_t)(n0 + row + q * 32) * KK
                                        + (c + 1) * 64 + seg * 8);
        }
        __syncthreads();

        // ---- compute chunk c: 4 k-steps of 16 ----
#pragma unroll
        for (int kk = 0; kk < 4; ++kk) {
            wmma::fragment<wmma::matrix_a, 16, 16, 16, __half, wmma::row_major> af[2];
            wmma::fragment<wmma::matrix_b, 16, 16, 16, __half, wmma::col_major> bf[4];
#pragma unroll
            for (int i = 0; i < 2; ++i)
                wmma::load_matrix_sync(af[i], As + (wm * 32 + i * 16) * LDA + kk * 16, LDA);
#pragma unroll
            for (int j = 0; j < 4; ++j)
                wmma::load_matrix_sync(bf[j], Bs + (wn * 64 + j * 16) * LDA + kk * 16, LDA);
#pragma unroll
            for (int i = 0; i < 2; ++i)
#pragma unroll
                for (int j = 0; j < 4; ++j)
                    wmma::mma_sync(acc[i][j], af[i], bf[j], acc[i][j]);
        }
        __syncthreads();
    }

    // ---- epilogue: accs -> SMEM (fp32, ld=132), then bias/act/store ----
    float* Cs = (float*)smem;   // 128 x 132 floats = 67584 B (reuses buffers)
#pragma unroll
    for (int i = 0; i < 2; ++i)
#pragma unroll
        for (int j = 0; j < 4; ++j)
            wmma::store_matrix_sync(Cs + (wm * 32 + i * 16) * 132 + wn * 64 + j * 16,
                                    acc[i][j], 132, wmma::mem_row_major);
    __syncthreads();

    const int r    = tid >> 1;
    const int half = tid & 1;
    const float* src = Cs + r * 132 + half * 64;
    const float* bsrc = bias_s + half * 64;
    if (STAGE == 1) {
        __half* dst = (__half*)Cg + (size_t)(m0 + r) * NDIM + n0 + half * 64;
#pragma unroll
        for (int j = 0; j < 64; j += 8) {
            uint4 o;
            float v0 = fmaxf(src[j+0] + bsrc[j+0], 0.f), v1 = fmaxf(src[j+1] + bsrc[j+1], 0.f);
            float v2 = fmaxf(src[j+2] + bsrc[j+2], 0.f), v3 = fmaxf(src[j+3] + bsrc[j+3], 0.f);
            float v4 = fmaxf(src[j+4] + bsrc[j+4], 0.f), v5 = fmaxf(src[j+5] + bsrc[j+5], 0.f);
            float v6 = fmaxf(src[j+6] + bsrc[j+6], 0.f), v7 = fmaxf(src[j+7] + bsrc[j+7], 0.f);
            o.x = pack_h2(__float2half_rn(v0), __float2half_rn(v1));
            o.y = pack_h2(__float2half_rn(v2), __float2half_rn(v3));
            o.z = pack_h2(__float2half_rn(v4), __float2half_rn(v5));
            o.w = pack_h2(__float2half_rn(v6), __float2half_rn(v7));
            *(uint4*)(dst + j) = o;
        }
    } else {
        float* dst = (float*)Cg + (size_t)(m0 + r) * NDIM + n0 + half * 64;
#pragma unroll
        for (int j = 0; j < 64; j += 4) {
            float4 o;
            o.x = src[j+0] + bsrc[j+0];
            o.y = src[j+1] + bsrc[j+1];
            o.z = src[j+2] + bsrc[j+2];
            o.w = src[j+3] + bsrc[j+3];
            *(float4*)(dst + j) = o;
        }
    }
}

// ---------------- Launch ----------------
extern "C" void kernel_launch(void* const* d_in, const int* in_sizes, int n_in,
                              void* d_out, int out_size) {
    const float* x  = (const float*)d_in[0];
    const float* G  = (const float*)d_in[1];
    const float* H  = (const float*)d_in[2];
    const float* b1 = (const float*)d_in[3];
    const float* W2 = (const float*)d_in[4];
    const float* b2 = (const float*)d_in[5];
    float* out = (float*)d_out;

    void *pWp = nullptr, *pWtd = nullptr, *pW2t = nullptr, *ph = nullptr;
    cudaGetSymbolAddress(&pWp, g_Wpart);
    cudaGetSymbolAddress(&pWtd, g_Wtd);
    cudaGetSymbolAddress(&pW2t, g_W2t);
    cudaGetSymbolAddress(&ph, g_h);

    cudaFuncSetAttribute(gemm_wmma<1>, cudaFuncAttributeMaxDynamicSharedMemorySize, SMEM_SZ);
    cudaFuncSetAttribute(gemm_wmma<2>, cudaFuncAttributeMaxDynamicSharedMemorySize, SMEM_SZ);

    krylov_part<<<dim3(8, 8, 16), 256>>>(G, H, (float*)pWp);
    pack_w<<<dim3(16, 16), dim3(32, 8)>>>((const float*)pWp, (__half*)pWtd);
    pack_w2<<<dim3(16, 16), dim3(32, 8)>>>(W2, (__half*)pW2t);

    gemm_wmma<1><<<dim3(4, BATCH / 128), 256, SMEM_SZ>>>(x, (const __half*)pWtd, b1, ph);
    gemm_wmma<2><<<dim3(4, BATCH / 128), 256, SMEM_SZ>>>(ph, (const __half*)pW2t, b2, out);
}

// round 5
// speedup vs baseline: 4.3959x; 1.4698x over previous
#include <cuda_runtime.h>
#include <cuda_fp16.h>
#include <mma.h>
#include <cstdint>
#include <cstddef>

using namespace nvcuda;

#define NDIM  512
#define BATCH 65536

// Scratch (__device__ globals: allocation-free rule)
__device__ float  g_Wpart[16 * NDIM * NDIM];   // 16 MB per-(i,j-quarter) partials
__device__ __half g_Wt [NDIM * NDIM];          // W^T  fp16 [n][k]
__device__ __half g_W2t[NDIM * NDIM];          // W2^T fp16 [n][k]
__device__ __half g_xh[(size_t)BATCH * NDIM];  // 64 MB x fp16
__device__ __half g_h [(size_t)BATCH * NDIM];  // 64 MB hidden fp16

__device__ __forceinline__ uint32_t pack_h2(__half a, __half b) {
    return (uint32_t)__half_as_ushort(a) | ((uint32_t)__half_as_ushort(b) << 16);
}
__device__ __forceinline__ uint32_t smem_u32(const void* p) {
    uint32_t a;
    asm("{ .reg .u64 t; cvta.to.shared.u64 t, %1; cvt.u32.u64 %0, t; }" : "=r"(a) : "l"(p));
    return a;
}
__device__ __forceinline__ void cp_async16(uint32_t dst, const void* src) {
    asm volatile("cp.async.cg.shared.global [%0], [%1], 16;" :: "r"(dst), "l"(src));
}
#define CP_COMMIT() asm volatile("cp.async.commit_group;" ::: "memory")
#define CP_WAIT(n)  asm volatile("cp.async.wait_group %0;" :: "n"(n) : "memory")

// ---------------- Kernel 0: x fp32 -> fp16 ----------------
__global__ __launch_bounds__(256)
void xconv(const float* __restrict__ x, __half* __restrict__ xh) {
    size_t i = ((size_t)blockIdx.x * 256 + threadIdx.x) * 8;
    float4 a = *(const float4*)(x + i);
    float4 b = *(const float4*)(x + i + 4);
    uint4 o;
    o.x = pack_h2(__float2half_rn(a.x), __float2half_rn(a.y));
    o.y = pack_h2(__float2half_rn(a.z), __float2half_rn(a.w));
    o.z = pack_h2(__float2half_rn(b.x), __float2half_rn(b.y));
    o.w = pack_h2(__float2half_rn(b.z), __float2half_rn(b.w));
    *(uint4*)(xh + i) = o;
}

// ---------------- Kernel 1: Krylov partial W (split by i and j-quarter) ----------------
// W[a,b] = sum_i sum_j ge_i[512+a-j] * hs_i[b+j]
__global__ __launch_bounds__(256)
void krylov_part(const float* __restrict__ G, const float* __restrict__ H,
                 float* __restrict__ Wp) {
    __shared__ float ge[1024], hs[1024];
    const int tid = threadIdx.x;
    const int i  = blockIdx.z & 3;
    const int j0 = (blockIdx.z >> 2) * 128;
    for (int k = tid; k < 1024; k += 256) {
        ge[k] = G[(k & 511) * 4 + i];
        hs[k] = (k < 512) ? H[k * 4 + i] : -H[(k - 512) * 4 + i];
    }
    __syncthreads();
    const int a0 = blockIdx.y * 64 + (tid >> 4) * 4;
    const int b0 = blockIdx.x * 64 + (tid & 15) * 4;
    float acc[4][4] = {};
    float ga[4], hb[4];
#pragma unroll
    for (int d = 0; d < 4; ++d) ga[d] = ge[512 + a0 + d - j0];
#pragma unroll
    for (int e = 0; e < 4; ++e) hb[e] = hs[b0 + e + j0];
#pragma unroll 4
    for (int j = j0; j < j0 + 128; ++j) {
#pragma unroll
        for (int d = 0; d < 4; ++d)
#pragma unroll
            for (int e = 0; e < 4; ++e)
                acc[d][e] = fmaf(ga[d], hb[e], acc[d][e]);
        ga[3] = ga[2]; ga[2] = ga[1]; ga[1] = ga[0];
        ga[0] = ge[512 + a0 - (j + 1)];
        hb[0] = hb[1]; hb[1] = hb[2]; hb[2] = hb[3];
        hb[3] = hs[b0 + 3 + (j + 1)];
    }
    float* Ws = Wp + (size_t)blockIdx.z * NDIM * NDIM;
#pragma unroll
    for (int d = 0; d < 4; ++d)
#pragma unroll
        for (int e = 0; e < 4; ++e)
            Ws[(a0 + d) * NDIM + (b0 + e)] = acc[d][e];
}

// -------- Kernel 2a: Wt[n][k] = fp16(sum_z Wpart[z][k][n]) --------
__global__ __launch_bounds__(256)
void pack_w(const float* __restrict__ Wp, __half* __restrict__ Wt) {
    __shared__ float t[32][33];
    const int bx = blockIdx.x * 32, by = blockIdx.y * 32, tx = threadIdx.x;
    for (int r = threadIdx.y; r < 32; r += 8) {
        size_t o = (size_t)(bx + r) * NDIM + by + tx;
        float s = 0.f;
#pragma unroll
        for (int z = 0; z < 16; ++z) s += Wp[o + (size_t)z * NDIM * NDIM];
        t[r][tx] = s;
    }
    __syncthreads();
    for (int r = threadIdx.y; r < 32; r += 8)
        Wt[(size_t)(by + r) * NDIM + bx + tx] = __float2half_rn(t[tx][r]);
}

// -------- Kernel 2b: W2t[n][k] = fp16(W2[k][n]) --------
__global__ __launch_bounds__(256)
void pack_w2(const float* __restrict__ W2, __half* __restrict__ W2t) {
    __shared__ float t[32][33];
    const int bx = blockIdx.x * 32, by = blockIdx.y * 32, tx = threadIdx.x;
    for (int r = threadIdx.y; r < 32; r += 8)
        t[r][tx] = W2[(size_t)(bx + r) * NDIM + by + tx];
    __syncthreads();
    for (int r = threadIdx.y; r < 32; r += 8)
        W2t[(size_t)(by + r) * NDIM + bx + tx] = __float2half_rn(t[tx][r]);
}

// ---------------- Kernel 3: wmma GEMM, 128x128 tile, cp.async 3-stage ----------------
// A [m][512] fp16, B [n][512] fp16 (both K-major). K-chunk 64.
// STAGE 1: C = relu(acc + b1) -> fp16 h.   STAGE 2: C = acc + b2 -> fp32 out.
#define LDA     72                  // halves per SMEM row (64 + 8 pad)
#define STG_SZ  36864u              // A tile (18432) + B tile (18432)
#define SBIAS   110592u             // after 3 stages
#define SMEM_SZ 111104u
#define NCHUNK  8

template <int STAGE>
__global__ __launch_bounds__(256, 2)
void gemm_wmma(const __half* __restrict__ Ag, const __half* __restrict__ Bg,
               const float* __restrict__ bias, void* __restrict__ Cg) {
    extern __shared__ char smem[];
    const uint32_t sb = smem_u32(smem);
    __half* smh = (__half*)smem;
    const int tid = threadIdx.x;
    const int wid = tid >> 5;
    const int wm = wid & 3;          // warp row (4)
    const int wn = wid >> 2;         // warp col (2)
    const int n0 = blockIdx.x * 128;
    const int m0 = blockIdx.y * 128;

    float* bias_s = (float*)(smem + SBIAS);
    if (tid < 128) bias_s[tid] = bias[n0 + tid];

    wmma::fragment<wmma::accumulator, 16, 16, 16, float> acc[2][4];
#pragma unroll
    for (int i = 0; i < 2; ++i)
#pragma unroll
        for (int j = 0; j < 4; ++j)
            wmma::fill_fragment(acc[i][j], 0.f);

    const int row = tid >> 3;        // 0..31 (x4 iters -> 128 rows)
    const int seg = tid & 7;         // 8 x 16B = 64 halves per row
    const __half* Abase = Ag + (size_t)m0 * NDIM;
    const __half* Bbase = Bg + (size_t)n0 * NDIM;

    // issue cp.async for chunk c into stage buffer c%3
    auto issue = [&](int c) {
        uint32_t buf = sb + (uint32_t)(c % 3) * STG_SZ;
        const __half* as = Abase + c * 64;
        const __half* bs = Bbase + c * 64;
#pragma unroll
        for (int q = 0; q < 4; ++q)
            cp_async16(buf + (row + q * 32) * (LDA * 2) + seg * 16,
                       as + (size_t)(row + q * 32) * NDIM + seg * 8);
#pragma unroll
        for (int q = 0; q < 4; ++q)
            cp_async16(buf + 18432u + (row + q * 32) * (LDA * 2) + seg * 16,
                       bs + (size_t)(row + q * 32) * NDIM + seg * 8);
    };

    issue(0); CP_COMMIT();
    issue(1); CP_COMMIT();

    for (int c = 0; c < NCHUNK; ++c) {
        if (c == NCHUNK - 1) CP_WAIT(0); else CP_WAIT(1);
        __syncthreads();
        if (c + 2 < NCHUNK) { issue(c + 2); CP_COMMIT(); }

        const __half* As = smh + ((c % 3) * STG_SZ) / 2;
        const __half* Bs = As + 18432 / 2;
#pragma unroll
        for (int kk = 0; kk < 4; ++kk) {
            wmma::fragment<wmma::matrix_a, 16, 16, 16, __half, wmma::row_major> af[2];
            wmma::fragment<wmma::matrix_b, 16, 16, 16, __half, wmma::col_major> bf[4];
#pragma unroll
            for (int i = 0; i < 2; ++i)
                wmma::load_matrix_sync(af[i], As + (wm * 32 + i * 16) * LDA + kk * 16, LDA);
#pragma unroll
            for (int j = 0; j < 4; ++j)
                wmma::load_matrix_sync(bf[j], Bs + (wn * 64 + j * 16) * LDA + kk * 16, LDA);
#pragma unroll
            for (int i = 0; i < 2; ++i)
#pragma unroll
                for (int j = 0; j < 4; ++j)
                    wmma::mma_sync(acc[i][j], af[i], bf[j], acc[i][j]);
        }
        __syncthreads();
    }

    // ---- epilogue: accs -> SMEM fp32 (ld=132), then bias/act/store ----
    float* Cs = (float*)smem;   // 128 x 132 x 4B = 67584 B (reuses stage buffers)
#pragma unroll
    for (int i = 0; i < 2; ++i)
#pragma unroll
        for (int j = 0; j < 4; ++j)
            wmma::store_matrix_sync(Cs + (wm * 32 + i * 16) * 132 + wn * 64 + j * 16,
                                    acc[i][j], 132, wmma::mem_row_major);
    __syncthreads();

    const int r    = tid >> 1;
    const int half = tid & 1;
    const float* src  = Cs + r * 132 + half * 64;
    const float* bsrc = bias_s + half * 64;
    if (STAGE == 1) {
        __half* dst = (__half*)Cg + (size_t)(m0 + r) * NDIM + n0 + half * 64;
#pragma unroll
        for (int j = 0; j < 64; j += 8) {
            uint4 o;
            float v0 = fmaxf(src[j+0] + bsrc[j+0], 0.f), v1 = fmaxf(src[j+1] + bsrc[j+1], 0.f);
            float v2 = fmaxf(src[j+2] + bsrc[j+2], 0.f), v3 = fmaxf(src[j+3] + bsrc[j+3], 0.f);
            float v4 = fmaxf(src[j+4] + bsrc[j+4], 0.f), v5 = fmaxf(src[j+5] + bsrc[j+5], 0.f);
            float v6 = fmaxf(src[j+6] + bsrc[j+6], 0.f), v7 = fmaxf(src[j+7] + bsrc[j+7], 0.f);
            o.x = pack_h2(__float2half_rn(v0), __float2half_rn(v1));
            o.y = pack_h2(__float2half_rn(v2), __float2half_rn(v3));
            o.z = pack_h2(__float2half_rn(v4), __float2half_rn(v5));
            o.w = pack_h2(__float2half_rn(v6), __float2half_rn(v7));
            *(uint4*)(dst + j) = o;
        }
    } else {
        float* dst = (float*)Cg + (size_t)(m0 + r) * NDIM + n0 + half * 64;
#pragma unroll
        for (int j = 0; j < 64; j += 4) {
            float4 o;
            o.x = src[j+0] + bsrc[j+0];
            o.y = src[j+1] + bsrc[j+1];
            o.z = src[j+2] + bsrc[j+2];
            o.w = src[j+3] + bsrc[j+3];
            *(float4*)(dst + j) = o;
        }
    }
}

// ---------------- Launch ----------------
extern "C" void kernel_launch(void* const* d_in, const int* in_sizes, int n_in,
                              void* d_out, int out_size) {
    const float* x  = (const float*)d_in[0];
    const float* G  = (const float*)d_in[1];
    const float* H  = (const float*)d_in[2];
    const float* b1 = (const float*)d_in[3];
    const float* W2 = (const float*)d_in[4];
    const float* b2 = (const float*)d_in[5];
    float* out = (float*)d_out;

    void *pWp, *pWt, *pW2t, *pxh, *ph;
    cudaGetSymbolAddress(&pWp, g_Wpart);
    cudaGetSymbolAddress(&pWt, g_Wt);
    cudaGetSymbolAddress(&pW2t, g_W2t);
    cudaGetSymbolAddress(&pxh, g_xh);
    cudaGetSymbolAddress(&ph, g_h);

    cudaFuncSetAttribute(gemm_wmma<1>, cudaFuncAttributeMaxDynamicSharedMemorySize, SMEM_SZ);
    cudaFuncSetAttribute(gemm_wmma<2>, cudaFuncAttributeMaxDynamicSharedMemorySize, SMEM_SZ);

    xconv<<<(BATCH * NDIM) / (256 * 8), 256>>>(x, (__half*)pxh);
    krylov_part<<<dim3(8, 8, 16), 256>>>(G, H, (float*)pWp);
    pack_w<<<dim3(16, 16), dim3(32, 8)>>>((const float*)pWp, (__half*)pWt);
    pack_w2<<<dim3(16, 16), dim3(32, 8)>>>(W2, (__half*)pW2t);

    gemm_wmma<1><<<dim3(4, BATCH / 128), 256, SMEM_SZ>>>((const __half*)pxh, (const __half*)pWt,  b1, ph);
    gemm_wmma<2><<<dim3(4, BATCH / 128), 256, SMEM_SZ>>>((const __half*)ph,  (const __half*)pW2t, b2, out);
}